// round 11
// baseline (speedup 1.0000x reference)
#include <cuda_runtime.h>

// diff[K, N, D] = x[None, :, :] - centroid[:, None, :]
// N=65536, K=32, D=64, fp32. Store-roofline: 536 MB out.
// Locked: KG=4 write streams, per-thread store MLP=4, __stcs, THREADS=256.
// (streams,MLP) matrix exhausted at ~76us. This round: per-CTA write
// CONTIGUITY. Each CTA owns CHUNKS=4 consecutive 4KB chunks per plane
// (16KB sequential run per plane per CTA) via idx-outer / k-inner loop.
// Streams, MLP, traffic unchanged; only DRAM row-run length per requester
// grows 4x.

#define N_PTS 65536
#define K_CENT 32
#define D_DIM 64
#define D4 (D_DIM / 4)            // 16 float4 per row
#define KG 4                      // k's per CTA (write streams)
#define KY (K_CENT / KG)          // gridDim.y = 8
#define CENT_F4 (KG * D4)         // 64 float4 = 1 KB staged per CTA
#define THREADS 256
#define CHUNKS 4                  // consecutive 4KB chunks per CTA

__global__ void __launch_bounds__(THREADS, 8)
kmeans_diff_kernel(const float4* __restrict__ x,
                   const float4* __restrict__ cent,
                   float4* __restrict__ out) {
    __shared__ float4 sc[CENT_F4];

    const int k0 = blockIdx.y * KG;

    // Stage this CTA's KG centroid rows (1 KB) into shared.
    for (int i = threadIdx.x; i < CENT_F4; i += blockDim.x)
        sc[i] = cent[k0 * D4 + i];
    __syncthreads();

    const size_t plane = (size_t)N_PTS * D4;   // float4 per k-plane
    const unsigned base = blockIdx.x * (CHUNKS * THREADS) + threadIdx.x;
    const unsigned d4 = base & (D4 - 1);       // invariant across chunks
                                               // (THREADS % D4 == 0)

    // Preload centroid values once (k-invariant across chunks).
    float4 cv[KG];
#pragma unroll
    for (int kk = 0; kk < KG; kk++)
        cv[kk] = sc[kk * D4 + d4];

#pragma unroll
    for (int ch = 0; ch < CHUNKS; ch++) {
        const unsigned idx = base + ch * THREADS;
        const float4 xv = x[idx];              // L2 hit after first wave

        float4* o = out + (size_t)k0 * plane + idx;
#pragma unroll
        for (int kk = 0; kk < KG; kk++) {
            const float4 c = cv[kk];
            float4 r;
            r.x = xv.x - c.x;
            r.y = xv.y - c.y;
            r.z = xv.z - c.z;
            r.w = xv.w - c.w;
            __stcs(o, r);                      // evict-first (proven optimal)
            o += plane;
        }
    }
}

extern "C" void kernel_launch(void* const* d_in, const int* in_sizes, int n_in,
                              void* d_out, int out_size) {
    const float4* x    = (const float4*)d_in[0];   // [N, D] fp32
    const float4* cent = (const float4*)d_in[1];   // [K, D] fp32
    float4* out        = (float4*)d_out;           // [K, N, D] fp32

    const int total_f4 = N_PTS * D4;               // 1,048,576
    dim3 grid(total_f4 / (CHUNKS * THREADS), KY);  // (1024, 8)
    kmeans_diff_kernel<<<grid, THREADS>>>(x, cent, out);
}

// round 12
// speedup vs baseline: 1.1524x; 1.1524x over previous
#include <cuda_runtime.h>

// diff[K, N, D] = x[None, :, :] - centroid[:, None, :]
// N=65536, K=32, D=64, fp32. Pure store-roofline problem: 536 MB out.
//
// CONVERGED CONFIG (full axis sweep on GB300):
//   K-split KG:   32->81.9us  8->78.0  4->76.3(min)  2->77.1
//   x-ILP:        1 (ILP=2 regressed at KG=32/4/2)
//   store policy: __stcs (default 92.9us — L2 dirty thrash; .wt 94.2us —
//                 loses LTS write coalescing; .cs = brief-residency sweet spot)
//   THREADS:      256 (512 tied within noise)
//   chunking:     none (idx-outer/k-inner serialized stores, 88.6us)
//
// 7.03 TB/s effective write stream = 88% of 8 TB/s spec; remaining gap is
// DRAM write-turnaround physics, confirmed non-addressable by stream count,
// MLP, policy, CTA shape, or contiguity.

#define N_PTS 65536
#define K_CENT 32
#define D_DIM 64
#define D4 (D_DIM / 4)            // 16 float4 per row
#define KG 4                      // k's per CTA (optimum)
#define KY (K_CENT / KG)          // gridDim.y = 8
#define CENT_F4 (KG * D4)         // 64 float4 = 1 KB staged per CTA
#define THREADS 256

__global__ void __launch_bounds__(THREADS, 8)
kmeans_diff_kernel(const float4* __restrict__ x,
                   const float4* __restrict__ cent,
                   float4* __restrict__ out) {
    __shared__ float4 sc[CENT_F4];

    const int k0 = blockIdx.y * KG;

    // Stage this CTA's KG centroid rows (1 KB) into shared.
    for (int i = threadIdx.x; i < CENT_F4; i += blockDim.x)
        sc[i] = cent[k0 * D4 + i];
    __syncthreads();

    const unsigned idx = blockIdx.x * THREADS + threadIdx.x;  // [0, N*D/4)
    const unsigned d4 = idx & (D4 - 1);

    const float4 xv = x[idx];  // DRAM first wave, L2 hit afterwards

    const size_t plane = (size_t)N_PTS * D4;  // float4 per k-plane
    float4* o = out + (size_t)k0 * plane + idx;

#pragma unroll
    for (int kk = 0; kk < KG; kk++) {
        const float4 c = sc[kk * D4 + d4];
        float4 r;
        r.x = xv.x - c.x;
        r.y = xv.y - c.y;
        r.z = xv.z - c.z;
        r.w = xv.w - c.w;
        __stcs(o, r);            // evict-first: proven optimal policy
        o += plane;
    }
}

extern "C" void kernel_launch(void* const* d_in, const int* in_sizes, int n_in,
                              void* d_out, int out_size) {
    const float4* x    = (const float4*)d_in[0];   // [N, D] fp32
    const float4* cent = (const float4*)d_in[1];   // [K, D] fp32
    float4* out        = (float4*)d_out;           // [K, N, D] fp32

    const int total_f4 = N_PTS * D4;               // 1,048,576
    dim3 grid(total_f4 / THREADS, KY);             // (4096, 8)
    kmeans_diff_kernel<<<grid, THREADS>>>(x, cent, out);
}